// round 9
// baseline (speedup 1.0000x reference)
#include <cuda_runtime.h>
#include <math_constants.h>

// Morphological opening: dilate3x3(erode3x3(x)), flat SE, geodesic SAME padding.
// x: (16,3,1024,1024) f32 -> 48 planes of 1024x1024.
//
// Fused, smem-free, register-pipelined, overlapped-tile (no halo loads):
//   - warp loads 128 cols (lane l holds cols 4l..4l+3 as float4), owns 124 valid
//     output cols; tiles stride by 124 (9 x-tiles, last anchored at 896)
//   - horizontal min3/max3 via warp shuffles; interior edge lanes masked at store
//   - vertical pad via clamp-to-edge row replication (identity for min windows);
//     dilation -inf pad handled on the two image-boundary g rows only
//   - INTERIOR FAST PATH: tiles with ty in [1,30] (94%) run a loop with no row
//     clamp and no in-image check; only ty==0 / ty==31 take the guarded loop
//   - __ldcg loads (halo reuse lives in L2, not L1)
//   - 3-deep row prefetch, 3-deep vertical rings, unroll 6 = lcm(3,2)
//   - TH=32 -> 6912 blocks of 64 thr at 16 blk/SM = 2.92 waves (tail ~3%)

#define TH      32
#define IMG_W   1024
#define IMG_H   1024
#define PLANES  48
#define TILES_X 9
#define TILE_STRIDE 124
#define TILES_Y (IMG_H / TH)    // 32

__device__ __forceinline__ float min3f(float a, float b, float c) {
    return fminf(a, fminf(b, c));
}
__device__ __forceinline__ float max3f(float a, float b, float c) {
    return fmaxf(a, fmaxf(b, c));
}

__global__ void __launch_bounds__(64, 16)
morph_open_kernel(const float* __restrict__ in, float* __restrict__ out) {
    const unsigned FULL = 0xffffffffu;
    const float INF  = CUDART_INF_F;
    const float NINF = -CUDART_INF_F;

    const int warp_g = blockIdx.x * 2 + (threadIdx.x >> 5);
    const int lane   = threadIdx.x & 31;

    const int tx = warp_g % TILES_X;
    const int ty = (warp_g / TILES_X) % TILES_Y;
    const int p  = warp_g / (TILES_X * TILES_Y);
    if (p >= PLANES) return;

    const float* __restrict__ base  = in  + (size_t)p * (IMG_W * IMG_H);
    float*       __restrict__ obase = out + (size_t)p * (IMG_W * IMG_H);

    // tile anchors: 0,124,...,868, then 896 (last tile right-aligned)
    const int x0 = (tx == TILES_X - 1) ? (IMG_W - 128) : tx * TILE_STRIDE;
    const int y0 = ty * TH;
    const int cbase = x0 + 4 * lane;
    const bool leftEdge  = (tx == 0);
    const bool rightEdge = (tx == TILES_X - 1);
    const bool isL = (lane == 0);
    const bool isR = (lane == 31);
    const bool storeFull = (!isL || leftEdge) && (!isR || rightEdge);

    // ---- horizontal min3 of one input row (shuffle-only)
    auto hminrow = [&](const float4& x, float4& h) {
        float xl = __shfl_up_sync(FULL, x.w, 1);
        if (isL) xl = INF;
        float xr = __shfl_down_sync(FULL, x.x, 1);
        if (isR) xr = INF;
        h.x = min3f(xl,  x.x, x.y);
        h.y = min3f(x.x, x.y, x.z);
        h.z = min3f(x.y, x.z, x.w);
        h.w = min3f(x.z, x.w, xr);
    };

    // ---- horizontal max3 of an erosion row (shuffle-only)
    auto hmaxrow = [&](const float4& e, float4& g) {
        float el = __shfl_up_sync(FULL, e.w, 1);
        if (isL) el = NINF;
        float er = __shfl_down_sync(FULL, e.x, 1);
        if (isR) er = NINF;
        g.x = max3f(el,  e.x, e.y);
        g.y = max3f(e.x, e.y, e.z);
        g.z = max3f(e.y, e.z, e.w);
        g.w = max3f(e.z, e.w, er);
    };

    // ---- main pipeline, parameterized on the row loader and the need for the
    //      in-image check on g rows (only image top/bottom tiles need it)
    auto mainloop = [&](auto loadrowF, bool noGuard) {
        float4 hA, hB, hC;
        {
            float4 t;
            loadrowF(y0 - 2, t); hminrow(t, hA);
            loadrowF(y0 - 1, t); hminrow(t, hB);
        }
        float4 gA = make_float4(NINF, NINF, NINF, NINF);
        float4 gB = gA;

        float4 n0, n1, n2;
        loadrowF(y0,     n0);
        loadrowF(y0 + 1, n1);
        loadrowF(y0 + 2, n2);

        #pragma unroll 6
        for (int r = y0 - 1; r <= y0 + TH; ++r) {
            const float4 cx = n0;
            n0 = n1; n1 = n2;
            loadrowF(r + 4, n2);

            hminrow(cx, hC);

            float4 e;
            e.x = min3f(hA.x, hB.x, hC.x);
            e.y = min3f(hA.y, hB.y, hC.y);
            e.z = min3f(hA.z, hB.z, hC.z);
            e.w = min3f(hA.w, hB.w, hC.w);

            float4 g;
            if (noGuard || (unsigned)r < (unsigned)IMG_H) {
                hmaxrow(e, g);
            } else {
                g = make_float4(NINF, NINF, NINF, NINF);
            }

            if (r - 1 >= y0) {
                float4 o;
                o.x = max3f(gA.x, gB.x, g.x);
                o.y = max3f(gA.y, gB.y, g.y);
                o.z = max3f(gA.z, gB.z, g.z);
                o.w = max3f(gA.w, gB.w, g.w);
                float* orow = obase + (size_t)(r - 1) * IMG_W + cbase;
                if (storeFull) {
                    __stcs(reinterpret_cast<float4*>(orow), o);
                } else if (isL) {
                    __stcs(reinterpret_cast<float2*>(orow + 2), make_float2(o.z, o.w));
                } else {  // isR, interior
                    __stcs(reinterpret_cast<float2*>(orow), make_float2(o.x, o.y));
                }
            }

            hA = hB; hB = hC;
            gA = gB; gB = g;
        }
    };

    if (ty != 0 && ty != TILES_Y - 1) {
        // interior tile: rows y0-2 .. y0+TH+4 all in [0, IMG_H) — no clamp, no guard
        auto fastload = [&](int r, float4& v) {
            v = __ldcg(reinterpret_cast<const float4*>(
                base + (size_t)r * IMG_W + cbase));
        };
        mainloop(fastload, true);
    } else {
        // image top/bottom tile: clamp-to-edge rows (identity for min windows),
        // explicit -inf on out-of-image g rows
        auto clampload = [&](int r, float4& v) {
            int rc = min(max(r, 0), IMG_H - 1);
            v = __ldcg(reinterpret_cast<const float4*>(
                base + (size_t)rc * IMG_W + cbase));
        };
        mainloop(clampload, false);
    }
}

extern "C" void kernel_launch(void* const* d_in, const int* in_sizes, int n_in,
                              void* d_out, int out_size) {
    const float* x = (const float*)d_in[0];
    float* o = (float*)d_out;
    // 48 planes * 32 y-tiles * 9 x-tiles = 13824 warps; 64-thread blocks (2 warps)
    const int total_warps = PLANES * TILES_Y * TILES_X;
    const int blocks = (total_warps * 32 + 63) / 64;   // 6912
    morph_open_kernel<<<blocks, 64>>>(x, o);
}